// round 5
// baseline (speedup 1.0000x reference)
#include <cuda_runtime.h>
#include <cuda_bf16.h>
#include <cstdint>

// Problem constants
#define Bb 128
#define Ss 128
#define Hh 1024
#define Ee 512
#define Vv 32000

// GEMM tile config: CTA 128x128, 4 warps, warp tile 64x64, BK=16
#define BM 128
#define BN 128
#define BK 16
#define SA 20          // padded smem row stride (floats); 80B rows keep 16B align
#define TILE_FLOATS (BM * SA)            // 2560 floats per A or B tile
#define STAGE_FLOATS (2 * TILE_FLOATS)   // 5120

// mode 0 (cp.async, 4 stages) — used by pred GEMM
#define STAGES 4
#define DSMEM_A (STAGES * STAGE_FLOATS * 4)   // 81920
// mode 1 (LDG->CVT->STS, 2 stages) — used by compute-bound GEMMs
#define DSMEM_B (2 * STAGE_FLOATS * 4)        // 40960

// ---------------- scratch (device globals; no allocation allowed) ----------
__device__ __align__(256) float g_x[Bb * 2560];        // [embeds | a]
__device__ __align__(256) float g_c1[Bb * 3584];       // [h_new | a | embeds]
__device__ __align__(256) float g_hb[Bb * Hh];         // dh @ W1h^T + b1
__device__ __align__(256) float g_part[8 * (Ss * Bb)]; // per-nblock partial scores
__device__ __align__(256) float g_alpha[Ss * Bb];      // softmax weights [s][b]
__device__ __align__(256) float g_gx[Bb * 3 * Hh];
__device__ __align__(256) float g_gh[Bb * 3 * Hh];

// ---------------- helpers ---------------------------------------------------
__device__ __forceinline__ uint32_t smem_u32(const void* p) {
    uint32_t a;
    asm("{ .reg .u64 t; cvta.to.shared.u64 t, %1; cvt.u32.u64 %0, t; }"
        : "=r"(a) : "l"(p));
    return a;
}

__device__ __forceinline__ uint32_t to_tf32_u(float x) {
    uint32_t u;
    asm("cvt.rna.tf32.f32 %0, %1;" : "=r"(u) : "f"(x));
    return u;
}
__device__ __forceinline__ float to_tf32_f(float x) {
    return __uint_as_float(to_tf32_u(x));
}

__device__ __forceinline__ void mma_tf32(float* c,
                                         uint32_t a0, uint32_t a1, uint32_t a2, uint32_t a3,
                                         uint32_t b0, uint32_t b1) {
    asm volatile(
        "mma.sync.aligned.m16n8k8.row.col.f32.tf32.tf32.f32 "
        "{%0,%1,%2,%3}, {%4,%5,%6,%7}, {%8,%9}, {%0,%1,%2,%3};"
        : "+f"(c[0]), "+f"(c[1]), "+f"(c[2]), "+f"(c[3])
        : "r"(a0), "r"(a1), "r"(a2), "r"(a3), "r"(b0), "r"(b1));
}

__device__ __forceinline__ void cp16(void* dst, const void* src) {
    asm volatile("cp.async.ca.shared.global [%0], [%1], 16;"
                 :: "r"(smem_u32(dst)), "l"(src));
}
__device__ __forceinline__ void cp_commit() {
    asm volatile("cp.async.commit_group;" ::: "memory");
}
template <int N>
__device__ __forceinline__ void cp_wait() {
    asm volatile("cp.async.wait_group %0;" :: "n"(N) : "memory");
}

__device__ __forceinline__ float tanh_fast(float x) {
    x = fminf(10.f, fmaxf(-10.f, x));
    const float t = __expf(2.f * x);
    return (t - 1.f) / (t + 1.f);
}

// ============================================================================
// Shared compute body: 64x64 warp tile, fragments straight from smem (values
// in smem are already tf32-rounded for mode 1; mode 0 converts at load).
// ============================================================================
template <int CVT_AT_LOAD>
__device__ __forceinline__ void compute_kb(const float* __restrict__ As,
                                           const float* __restrict__ Bs,
                                           float c[4][8][4],
                                           int wm, int wn, int r, int q) {
#pragma unroll
    for (int ks = 0; ks < 2; ks++) {
        const int k0 = ks * 8;
        uint32_t af[4][4];
#pragma unroll
        for (int mf = 0; mf < 4; mf++) {
            const int mb = (wm * 64 + mf * 16) * SA;
            if (CVT_AT_LOAD) {
                af[mf][0] = to_tf32_u(As[mb + r * SA + k0 + q]);
                af[mf][1] = to_tf32_u(As[mb + (r + 8) * SA + k0 + q]);
                af[mf][2] = to_tf32_u(As[mb + r * SA + k0 + q + 4]);
                af[mf][3] = to_tf32_u(As[mb + (r + 8) * SA + k0 + q + 4]);
            } else {
                af[mf][0] = __float_as_uint(As[mb + r * SA + k0 + q]);
                af[mf][1] = __float_as_uint(As[mb + (r + 8) * SA + k0 + q]);
                af[mf][2] = __float_as_uint(As[mb + r * SA + k0 + q + 4]);
                af[mf][3] = __float_as_uint(As[mb + (r + 8) * SA + k0 + q + 4]);
            }
        }
#pragma unroll
        for (int nf = 0; nf < 8; nf++) {
            const int nb = (wn * 64 + nf * 8 + r) * SA;
            uint32_t b0, b1;
            if (CVT_AT_LOAD) {
                b0 = to_tf32_u(Bs[nb + k0 + q]);
                b1 = to_tf32_u(Bs[nb + k0 + q + 4]);
            } else {
                b0 = __float_as_uint(Bs[nb + k0 + q]);
                b1 = __float_as_uint(Bs[nb + k0 + q + 4]);
            }
#pragma unroll
            for (int mf = 0; mf < 4; mf++)
                mma_tf32(c[mf][nf], af[mf][0], af[mf][1], af[mf][2], af[mf][3], b0, b1);
        }
    }
}

// Epilogues (shared by both GEMM variants)
template <int EPI>
__device__ __forceinline__ void epilogue(float c[4][8][4],
                                         const float* __restrict__ bias,
                                         float* __restrict__ out,
                                         int M, int ldc, int m0, int n0,
                                         const float* __restrict__ hb,
                                         const float* __restrict__ W2,
                                         float (*red)[2],
                                         int tid, int wm, int wn, int r, int q,
                                         int bx) {
    if (EPI == 0) {
#pragma unroll
        for (int mf = 0; mf < 4; mf++)
#pragma unroll
            for (int rr = 0; rr < 2; rr++) {
                const int mg = m0 + wm * 64 + mf * 16 + rr * 8 + r;
#pragma unroll
                for (int nf = 0; nf < 8; nf++) {
                    const int ng = n0 + wn * 64 + nf * 8 + q * 2;
                    float2 v;
                    v.x = c[mf][nf][rr * 2 + 0] + bias[ng];
                    v.y = c[mf][nf][rr * 2 + 1] + bias[ng + 1];
                    *(float2*)&out[(size_t)mg * ldc + ng] = v;
                }
            }
    } else {
        float rs[4][2];
#pragma unroll
        for (int mf = 0; mf < 4; mf++)
#pragma unroll
            for (int rr = 0; rr < 2; rr++) {
                const int row = wm * 64 + mf * 16 + rr * 8 + r; // == b
                float acc = 0.f;
#pragma unroll
                for (int nf = 0; nf < 8; nf++) {
                    const int ng = n0 + wn * 64 + nf * 8 + q * 2;
                    const float h0 = hb[row * Hh + ng];
                    const float h1 = hb[row * Hh + ng + 1];
                    acc += tanh_fast(c[mf][nf][rr * 2 + 0] + h0) * W2[ng];
                    acc += tanh_fast(c[mf][nf][rr * 2 + 1] + h1) * W2[ng + 1];
                }
                rs[mf][rr] = acc;
            }
#pragma unroll
        for (int mf = 0; mf < 4; mf++)
#pragma unroll
            for (int rr = 0; rr < 2; rr++) {
                rs[mf][rr] += __shfl_xor_sync(0xffffffffu, rs[mf][rr], 1);
                rs[mf][rr] += __shfl_xor_sync(0xffffffffu, rs[mf][rr], 2);
            }
        if (q == 0) {
#pragma unroll
            for (int mf = 0; mf < 4; mf++)
#pragma unroll
                for (int rr = 0; rr < 2; rr++)
                    red[wm * 64 + mf * 16 + rr * 8 + r][wn] = rs[mf][rr];
        }
        __syncthreads();
        if (tid < BM)
            out[(size_t)bx * M + m0 + tid] = red[tid][0] + red[tid][1];
    }
}

// ============================================================================
// Variant A (mode 0): cp.async 4-stage pipeline, tf32 cvt at fragment load.
// Used for the HBM-bound pred GEMM.
// ============================================================================
__device__ __forceinline__ void fill_stage_cp(float* sA, float* sB,
                                              const float* __restrict__ A,
                                              const float* __restrict__ Bw,
                                              int m0, int n0, int lda, int ldb,
                                              int k0, int tid) {
#pragma unroll
    for (int h = 0; h < 4; h++) {
        const int c   = tid + h * 128;
        const int row = c >> 2;
        const int c4  = c & 3;
        cp16(sA + row * SA + c4 * 4, A  + (size_t)(m0 + row) * lda + k0 + c4 * 4);
        cp16(sB + row * SA + c4 * 4, Bw + (size_t)(n0 + row) * ldb + k0 + c4 * 4);
    }
}

template <int EPI>
__global__ __launch_bounds__(128)
void gemm_cp(const float* __restrict__ A, const float* __restrict__ Bw,
             const float* __restrict__ bias, float* __restrict__ out,
             int M, int K, int lda, int ldb, int ldc,
             const float* __restrict__ hb, const float* __restrict__ W2) {
    extern __shared__ __align__(16) float dyn[];
    __shared__ float red[BM][2];

    const int tid  = threadIdx.x;
    const int lane = tid & 31;
    const int wid  = tid >> 5;
    const int wm   = wid >> 1, wn = wid & 1;
    const int r    = lane >> 2, q = lane & 3;
    const int m0 = blockIdx.y * BM;
    const int n0 = blockIdx.x * BN;
    const int nK = K / BK;

    float c[4][8][4];
#pragma unroll
    for (int i = 0; i < 4; i++)
#pragma unroll
        for (int j = 0; j < 8; j++)
#pragma unroll
            for (int k = 0; k < 4; k++) c[i][j][k] = 0.f;

#pragma unroll
    for (int s = 0; s < STAGES - 1; s++) {
        fill_stage_cp(dyn + s * STAGE_FLOATS, dyn + s * STAGE_FLOATS + TILE_FLOATS,
                      A, Bw, m0, n0, lda, ldb, s * BK, tid);
        cp_commit();
    }

    for (int kb = 0; kb < nK; kb++) {
        cp_wait<STAGES - 2>();
        __syncthreads();
        {
            const int pf = kb + STAGES - 1;
            if (pf < nK) {
                const int ps = pf & (STAGES - 1);
                fill_stage_cp(dyn + ps * STAGE_FLOATS,
                              dyn + ps * STAGE_FLOATS + TILE_FLOATS,
                              A, Bw, m0, n0, lda, ldb, pf * BK, tid);
            }
            cp_commit();
        }
        const float* As = dyn + (kb & (STAGES - 1)) * STAGE_FLOATS;
        compute_kb<1>(As, As + TILE_FLOATS, c, wm, wn, r, q);
    }
    epilogue<EPI>(c, bias, out, M, ldc, m0, n0, hb, W2, red, tid, wm, wn, r, q,
                  blockIdx.x);
}

// ============================================================================
// Variant B (mode 1): LDG.128 -> cvt.rna.tf32 -> STS.128 fill, 2-stage smem,
// 1-ahead register prefetch, one barrier per kb. MMA operands read straight
// from smem (already tf32) — NO cvt on the critical path.
// ============================================================================
template <int EPI>
__global__ __launch_bounds__(128)
void gemm_ld(const float* __restrict__ A, const float* __restrict__ Bw,
             const float* __restrict__ bias, float* __restrict__ out,
             int M, int K, int lda, int ldb, int ldc,
             const float* __restrict__ hb, const float* __restrict__ W2) {
    extern __shared__ __align__(16) float dyn[];
    __shared__ float red[BM][2];

    const int tid  = threadIdx.x;
    const int lane = tid & 31;
    const int wid  = tid >> 5;
    const int wm   = wid >> 1, wn = wid & 1;
    const int r    = lane >> 2, q = lane & 3;
    const int m0 = blockIdx.y * BM;
    const int n0 = blockIdx.x * BN;
    const int nK = K / BK;

    // per-thread load geometry (4 chunks per tile)
    int rowv[4], c4v[4];
#pragma unroll
    for (int h = 0; h < 4; h++) {
        const int c = tid + h * 128;
        rowv[h] = c >> 2;
        c4v[h]  = c & 3;
    }

    float c[4][8][4];
#pragma unroll
    for (int i = 0; i < 4; i++)
#pragma unroll
        for (int j = 0; j < 8; j++)
#pragma unroll
            for (int k = 0; k < 4; k++) c[i][j][k] = 0.f;

    float4 ra[4], rb[4];

    // prologue: load k-block 0, convert, store to stage 0
#pragma unroll
    for (int h = 0; h < 4; h++) {
        ra[h] = *(const float4*)(A  + (size_t)(m0 + rowv[h]) * lda + c4v[h] * 4);
        rb[h] = *(const float4*)(Bw + (size_t)(n0 + rowv[h]) * ldb + c4v[h] * 4);
    }
#pragma unroll
    for (int h = 0; h < 4; h++) {
        float4 wa, wb;
        wa.x = to_tf32_f(ra[h].x); wa.y = to_tf32_f(ra[h].y);
        wa.z = to_tf32_f(ra[h].z); wa.w = to_tf32_f(ra[h].w);
        wb.x = to_tf32_f(rb[h].x); wb.y = to_tf32_f(rb[h].y);
        wb.z = to_tf32_f(rb[h].z); wb.w = to_tf32_f(rb[h].w);
        *(float4*)&dyn[rowv[h] * SA + c4v[h] * 4]               = wa;
        *(float4*)&dyn[TILE_FLOATS + rowv[h] * SA + c4v[h] * 4] = wb;
    }
    __syncthreads();

    for (int kb = 0; kb < nK; kb++) {
        const bool more = (kb + 1 < nK);
        if (more) {
            const int ko = (kb + 1) * BK;
#pragma unroll
            for (int h = 0; h < 4; h++) {
                ra[h] = *(const float4*)(A  + (size_t)(m0 + rowv[h]) * lda + ko + c4v[h] * 4);
                rb[h] = *(const float4*)(Bw + (size_t)(n0 + rowv[h]) * ldb + ko + c4v[h] * 4);
            }
        }

        const float* As = dyn + (kb & 1) * STAGE_FLOATS;
        compute_kb<0>(As, As + TILE_FLOATS, c, wm, wn, r, q);

        if (more) {
            float* Dn = dyn + ((kb + 1) & 1) * STAGE_FLOATS;
#pragma unroll
            for (int h = 0; h < 4; h++) {
                float4 wa, wb;
                wa.x = to_tf32_f(ra[h].x); wa.y = to_tf32_f(ra[h].y);
                wa.z = to_tf32_f(ra[h].z); wa.w = to_tf32_f(ra[h].w);
                wb.x = to_tf32_f(rb[h].x); wb.y = to_tf32_f(rb[h].y);
                wb.z = to_tf32_f(rb[h].z); wb.w = to_tf32_f(rb[h].w);
                *(float4*)&Dn[rowv[h] * SA + c4v[h] * 4]               = wa;
                *(float4*)&Dn[TILE_FLOATS + rowv[h] * SA + c4v[h] * 4] = wb;
            }
        }
        __syncthreads();
    }
    epilogue<EPI>(c, bias, out, M, ldc, m0, n0, hb, W2, red, tid, wm, wn, r, q,
                  blockIdx.x);
}

// ---------------- small kernels ---------------------------------------------
__global__ void k_embed(const int* __restrict__ tl, const float* __restrict__ emb,
                        float* __restrict__ x, float* __restrict__ c1) {
    const int b = blockIdx.x;
    const int e = threadIdx.x; // 512
    const float v = emb[(size_t)tl[b] * Ee + e];
    x[b * 2560 + e] = v;
    c1[b * 3584 + 3072 + e] = v;
}

__global__ void k_softmax(const float* __restrict__ part, float* __restrict__ alpha) {
    const int b = blockIdx.x;
    const int s = threadIdx.x; // 128
    float sc = 0.f;
#pragma unroll
    for (int p = 0; p < 8; p++) sc += part[p * (Ss * Bb) + s * Bb + b];
    __shared__ float sh[Ss];
    sh[s] = sc; __syncthreads();
    for (int off = 64; off > 0; off >>= 1) {
        if (s < off) sh[s] = fmaxf(sh[s], sh[s + off]);
        __syncthreads();
    }
    const float mx = sh[0]; __syncthreads();
    const float e = __expf(sc - mx);
    sh[s] = e; __syncthreads();
    for (int off = 64; off > 0; off >>= 1) {
        if (s < off) sh[s] += sh[s + off];
        __syncthreads();
    }
    alpha[s * Bb + b] = e / sh[0];
}

__global__ void k_context(const float* __restrict__ enc, const float* __restrict__ alpha,
                          float* __restrict__ x, float* __restrict__ c1) {
    const int b = blockIdx.x;
    const int t = threadIdx.x; // 512
    float a0 = 0.f, a1 = 0.f, a2 = 0.f, a3 = 0.f;
    for (int s = 0; s < Ss; s++) {
        const float al = alpha[s * Bb + b];
        const float* e = enc + (size_t)(s * Bb + b) * 2048 + t;
        a0 += al * e[0];
        a1 += al * e[512];
        a2 += al * e[1024];
        a3 += al * e[1536];
    }
    x[b * 2560 + 512 + t]        = a0;  c1[b * 3584 + 1024 + t]        = a0;
    x[b * 2560 + 512 + 512 + t]  = a1;  c1[b * 3584 + 1024 + 512 + t]  = a1;
    x[b * 2560 + 512 + 1024 + t] = a2;  c1[b * 3584 + 1024 + 1024 + t] = a2;
    x[b * 2560 + 512 + 1536 + t] = a3;  c1[b * 3584 + 1024 + 1536 + t] = a3;
}

__global__ void k_gru(const float* __restrict__ dh, const float* __restrict__ gx,
                      const float* __restrict__ gh, float* __restrict__ hout,
                      float* __restrict__ c1) {
    const int b = blockIdx.x;
    const int h = threadIdx.x; // 1024
    const float xr = gx[b * 3072 + h],        hr = gh[b * 3072 + h];
    const float xz = gx[b * 3072 + 1024 + h], hz = gh[b * 3072 + 1024 + h];
    const float xn = gx[b * 3072 + 2048 + h], hn = gh[b * 3072 + 2048 + h];
    const float rg = 1.f / (1.f + __expf(-(xr + hr)));
    const float zg = 1.f / (1.f + __expf(-(xz + hz)));
    const float ng = tanh_fast(xn + rg * hn);
    const float hv = (1.f - zg) * ng + zg * dh[b * Hh + h];
    hout[b * Hh + h] = hv;
    c1[b * 3584 + h] = hv;
}

// ---------------- launch ----------------------------------------------------
extern "C" void kernel_launch(void* const* d_in, const int* in_sizes, int n_in,
                              void* d_out, int out_size) {
    const int*   tl   = (const int*)d_in[0];
    const float* dh   = (const float*)d_in[1];
    const float* enc  = (const float*)d_in[2];
    const float* emb  = (const float*)d_in[3];
    const float* W1   = (const float*)d_in[4];
    const float* b1   = (const float*)d_in[5];
    const float* W2   = (const float*)d_in[6];
    // d_in[7] = b2 (softmax-invariant, skipped)
    const float* Wih  = (const float*)d_in[8];
    const float* Whh  = (const float*)d_in[9];
    const float* bih  = (const float*)d_in[10];
    const float* bhh  = (const float*)d_in[11];
    const float* Wout = (const float*)d_in[12];
    const float* bout = (const float*)d_in[13];

    float* pred = (float*)d_out;                 // [128, 32000]
    float* hout = pred + (size_t)Bb * Vv;        // [128, 1024]

    float *x, *c1, *hb, *part, *alpha, *gx, *gh;
    cudaGetSymbolAddress((void**)&x,     g_x);
    cudaGetSymbolAddress((void**)&c1,    g_c1);
    cudaGetSymbolAddress((void**)&hb,    g_hb);
    cudaGetSymbolAddress((void**)&part,  g_part);
    cudaGetSymbolAddress((void**)&alpha, g_alpha);
    cudaGetSymbolAddress((void**)&gx,    g_gx);
    cudaGetSymbolAddress((void**)&gh,    g_gh);

    cudaFuncSetAttribute(gemm_cp<0>, cudaFuncAttributeMaxDynamicSharedMemorySize, DSMEM_A);
    cudaFuncSetAttribute(gemm_ld<0>, cudaFuncAttributeMaxDynamicSharedMemorySize, DSMEM_B);
    cudaFuncSetAttribute(gemm_ld<1>, cudaFuncAttributeMaxDynamicSharedMemorySize, DSMEM_B);

    // 1) embeddings -> x[:, :512], c1[:, 3072:]
    k_embed<<<Bb, 512>>>(tl, emb, x, c1);

    // 2) hb = dh @ W1[:, 2048:3072]^T + b1   (M=128, N=1024, K=1024)
    gemm_ld<0><<<dim3(8, 1), 128, DSMEM_B>>>(dh, W1 + 2048, b1, hb,
                                             Bb, Hh, Hh, 3 * Hh, Hh,
                                             nullptr, nullptr);

    // 3) energy GEMM + fused tanh*W2 reduction (M=16384, N=1024, K=2048)
    gemm_ld<1><<<dim3(8, 128), 128, DSMEM_B>>>(enc, W1, nullptr, part,
                                               Ss * Bb, 2 * Hh, 2 * Hh, 3 * Hh, 0,
                                               hb, W2);

    // 4) combine partials + softmax over s  -> alpha[s][b]
    k_softmax<<<Bb, Ss>>>(part, alpha);

    // 5) context a = sum_s alpha * enc -> x[:, 512:], c1[:, 1024:3072]
    k_context<<<Bb, 512>>>(enc, alpha, x, c1);

    // 6) gx = x @ Wih^T + bih   (M=128, N=3072, K=2560)
    gemm_ld<0><<<dim3(24, 1), 128, DSMEM_B>>>(x, Wih, bih, gx,
                                              Bb, 2560, 2560, 2560, 3 * Hh,
                                              nullptr, nullptr);

    // 7) gh = dh @ Whh^T + bhh  (M=128, N=3072, K=1024)
    gemm_ld<0><<<dim3(24, 1), 128, DSMEM_B>>>(dh, Whh, bhh, gh,
                                              Bb, Hh, Hh, Hh, 3 * Hh,
                                              nullptr, nullptr);

    // 8) GRU elementwise -> h_new (output tail) and c1[:, :1024]
    k_gru<<<Bb, Hh>>>(dh, gx, gh, hout, c1);

    // 9) pred = c1 @ Wout^T + bout  (M=128, N=32000, K=3584)  — HBM-bound,
    //    keep deep cp.async pipeline
    gemm_cp<0><<<dim3(250, 1), 128, DSMEM_A>>>(c1, Wout, bout, pred,
                                               Bb, 3584, 3584, 3584, Vv,
                                               nullptr, nullptr);
}

// round 6
// speedup vs baseline: 1.3257x; 1.3257x over previous
#include <cuda_runtime.h>
#include <cuda_fp16.h>
#include <cstdint>

// Problem constants
#define Bb 128
#define Ss 128
#define Hh 1024
#define Ee 512
#define Vv 32000

// fp16 GEMM tile config: CTA 128x128, 4 warps, warp tile 64x64, BK=32, 3 stages
#define BM 128
#define BN 128
#define BK 32
#define SAH 40                       // padded smem row stride in halfs (80B rows)
#define TILE_H (BM * SAH)            // 5120 halfs per A or B tile
#define STAGE_H (2 * TILE_H)         // 10240 halfs per stage
#define NSTG 3
#define DSMEM_BYTES (NSTG * STAGE_H * 2)   // 61440

// ---------------- scratch (device globals; no allocation allowed) ----------
__device__ __align__(256) float g_x[Bb * 2560];        // [embeds | a]
__device__ __align__(256) float g_c1[Bb * 3584];       // [h_new | a | embeds]
__device__ __align__(256) float g_hb[Bb * Hh];         // dh @ W1h^T + b1
__device__ __align__(256) float g_part[8 * (Ss * Bb)]; // per-nblock partial scores
__device__ __align__(256) float g_alpha[Ss * Bb];      // softmax weights [s][b]
__device__ __align__(256) float g_gx[Bb * 3 * Hh];
__device__ __align__(256) float g_gh[Bb * 3 * Hh];

// ---------------- helpers ---------------------------------------------------
__device__ __forceinline__ void mma_f16(float* c,
                                        uint32_t a0, uint32_t a1, uint32_t a2, uint32_t a3,
                                        uint32_t b0, uint32_t b1) {
    asm volatile(
        "mma.sync.aligned.m16n8k16.row.col.f32.f16.f16.f32 "
        "{%0,%1,%2,%3}, {%4,%5,%6,%7}, {%8,%9}, {%0,%1,%2,%3};"
        : "+f"(c[0]), "+f"(c[1]), "+f"(c[2]), "+f"(c[3])
        : "r"(a0), "r"(a1), "r"(a2), "r"(a3), "r"(b0), "r"(b1));
}

__device__ __forceinline__ float tanh_fast(float x) {
    x = fminf(10.f, fmaxf(-10.f, x));
    const float t = __expf(2.f * x);
    return (t - 1.f) / (t + 1.f);
}

__device__ __forceinline__ uint2 cvt_f4_h4(float4 v) {
    half2 h0 = __floats2half2_rn(v.x, v.y);
    half2 h1 = __floats2half2_rn(v.z, v.w);
    uint2 u;
    u.x = *reinterpret_cast<uint32_t*>(&h0);
    u.y = *reinterpret_cast<uint32_t*>(&h1);
    return u;
}

// ---------------- fp16 GEMM: out[M,N] = A[M,K] @ Bw[N,K]^T -------------------
// A, Bw fp32 in global; converted to fp16 (rn) once at fill time.
// 4 warps, warp tile 64x64 (mf=4 x nf=8), BK=32 => 2 k-steps of m16n8k16.
// EPI 0: out[m*ldc+n] = acc + bias[n]
// EPI 1: partial[bx*M + m] = sum_n tanh(acc + hb[(m%128)*H + n]) * W2[n]
template <int EPI>
__global__ __launch_bounds__(128, 2)
void gemm_h(const float* __restrict__ A, const float* __restrict__ Bw,
            const float* __restrict__ bias, float* __restrict__ out,
            int M, int K, int lda, int ldb, int ldc,
            const float* __restrict__ hb, const float* __restrict__ W2) {
    extern __shared__ __align__(16) __half dynh[];
    __shared__ float red[BM][2];

    const int tid  = threadIdx.x;
    const int lane = tid & 31;
    const int wid  = tid >> 5;
    const int wm   = wid >> 1, wn = wid & 1;
    const int r    = lane >> 2, q = lane & 3;
    const int m0 = blockIdx.y * BM;
    const int n0 = blockIdx.x * BN;
    const int nK = K / BK;

    // per-thread fill geometry: 8 chunks of 4 elements per tile
    int rowv[8], gv[8];
#pragma unroll
    for (int h = 0; h < 8; h++) {
        const int idx = tid + h * 128;   // 0..1023
        rowv[h] = idx >> 3;
        gv[h]   = idx & 7;
    }

    float c[4][8][4];
#pragma unroll
    for (int i = 0; i < 4; i++)
#pragma unroll
        for (int j = 0; j < 8; j++)
#pragma unroll
            for (int k = 0; k < 4; k++) c[i][j][k] = 0.f;

    uint2 sa[8], sb[8];

    // load + convert k-block kb into registers
    auto load_cvt = [&](int kb) {
        const int ko = kb * BK;
#pragma unroll
        for (int h = 0; h < 8; h++) {
            sa[h] = cvt_f4_h4(*(const float4*)(A  + (size_t)(m0 + rowv[h]) * lda + ko + gv[h] * 4));
            sb[h] = cvt_f4_h4(*(const float4*)(Bw + (size_t)(n0 + rowv[h]) * ldb + ko + gv[h] * 4));
        }
    };
    // store registers into smem stage
    auto sts = [&](int stage) {
        __half* D = dynh + stage * STAGE_H;
#pragma unroll
        for (int h = 0; h < 8; h++) {
            const int off = rowv[h] * SAH + gv[h] * 4;
            *(uint2*)(D + off)          = sa[h];
            *(uint2*)(D + TILE_H + off) = sb[h];
        }
    };

    // prologue
    load_cvt(0);
    sts(0);
    load_cvt(1);
    __syncthreads();

    int stg = 0;                      // stage holding k-block kb
    for (int kb = 0; kb < nK; kb++) {
        const int wstg = (stg + 1 == NSTG) ? 0 : stg + 1;
        if (kb + 1 < nK) sts(wstg);          // regs currently hold kb+1
        if (kb + 2 < nK) load_cvt(kb + 2);   // prefetch kb+2 into regs

        const __half* As = dynh + stg * STAGE_H;
        const __half* Bs = As + TILE_H;

#pragma unroll
        for (int ks = 0; ks < 2; ks++) {
            const int k0 = ks * 16 + 2 * q;
            uint32_t af[4][4];
#pragma unroll
            for (int mf = 0; mf < 4; mf++) {
                const int mb = wm * 64 + mf * 16;
                af[mf][0] = *(const uint32_t*)(As + (mb + r) * SAH + k0);
                af[mf][1] = *(const uint32_t*)(As + (mb + r + 8) * SAH + k0);
                af[mf][2] = *(const uint32_t*)(As + (mb + r) * SAH + k0 + 8);
                af[mf][3] = *(const uint32_t*)(As + (mb + r + 8) * SAH + k0 + 8);
            }
#pragma unroll
            for (int nf = 0; nf < 8; nf++) {
                const int nb = (wn * 64 + nf * 8 + r) * SAH;
                const uint32_t b0 = *(const uint32_t*)(Bs + nb + k0);
                const uint32_t b1 = *(const uint32_t*)(Bs + nb + k0 + 8);
#pragma unroll
                for (int mf = 0; mf < 4; mf++)
                    mma_f16(c[mf][nf], af[mf][0], af[mf][1], af[mf][2], af[mf][3], b0, b1);
            }
        }
        stg = wstg;
        __syncthreads();
    }

    if (EPI == 0) {
#pragma unroll
        for (int mf = 0; mf < 4; mf++)
#pragma unroll
            for (int rr = 0; rr < 2; rr++) {
                const int mg = m0 + wm * 64 + mf * 16 + rr * 8 + r;
#pragma unroll
                for (int nf = 0; nf < 8; nf++) {
                    const int ng = n0 + wn * 64 + nf * 8 + q * 2;
                    float2 v;
                    v.x = c[mf][nf][rr * 2 + 0] + bias[ng];
                    v.y = c[mf][nf][rr * 2 + 1] + bias[ng + 1];
                    *(float2*)&out[(size_t)mg * ldc + ng] = v;
                }
            }
    } else {
        // energy epilogue: tanh(acc + hb[b,n]) * W2[n], reduce over CTA n-range
        float rs[4][2];
#pragma unroll
        for (int mf = 0; mf < 4; mf++)
#pragma unroll
            for (int rr = 0; rr < 2; rr++) {
                const int row = wm * 64 + mf * 16 + rr * 8 + r; // == b
                float acc = 0.f;
#pragma unroll
                for (int nf = 0; nf < 8; nf++) {
                    const int ng = n0 + wn * 64 + nf * 8 + q * 2;
                    const float h0 = hb[row * Hh + ng];
                    const float h1 = hb[row * Hh + ng + 1];
                    acc += tanh_fast(c[mf][nf][rr * 2 + 0] + h0) * W2[ng];
                    acc += tanh_fast(c[mf][nf][rr * 2 + 1] + h1) * W2[ng + 1];
                }
                rs[mf][rr] = acc;
            }
#pragma unroll
        for (int mf = 0; mf < 4; mf++)
#pragma unroll
            for (int rr = 0; rr < 2; rr++) {
                rs[mf][rr] += __shfl_xor_sync(0xffffffffu, rs[mf][rr], 1);
                rs[mf][rr] += __shfl_xor_sync(0xffffffffu, rs[mf][rr], 2);
            }
        if (q == 0) {
#pragma unroll
            for (int mf = 0; mf < 4; mf++)
#pragma unroll
                for (int rr = 0; rr < 2; rr++)
                    red[wm * 64 + mf * 16 + rr * 8 + r][wn] = rs[mf][rr];
        }
        __syncthreads();
        if (tid < BM)
            out[(size_t)blockIdx.x * M + m0 + tid] = red[tid][0] + red[tid][1];
    }
}

// ---------------- small kernels ---------------------------------------------
__global__ void k_embed(const int* __restrict__ tl, const float* __restrict__ emb,
                        float* __restrict__ x, float* __restrict__ c1) {
    const int b = blockIdx.x;
    const int e = threadIdx.x; // 512
    const float v = emb[(size_t)tl[b] * Ee + e];
    x[b * 2560 + e] = v;
    c1[b * 3584 + 3072 + e] = v;
}

__global__ void k_softmax(const float* __restrict__ part, float* __restrict__ alpha) {
    const int b = blockIdx.x;
    const int s = threadIdx.x; // 128
    float sc = 0.f;
#pragma unroll
    for (int p = 0; p < 8; p++) sc += part[p * (Ss * Bb) + s * Bb + b];
    __shared__ float sh[Ss];
    sh[s] = sc; __syncthreads();
    for (int off = 64; off > 0; off >>= 1) {
        if (s < off) sh[s] = fmaxf(sh[s], sh[s + off]);
        __syncthreads();
    }
    const float mx = sh[0]; __syncthreads();
    const float e = __expf(sc - mx);
    sh[s] = e; __syncthreads();
    for (int off = 64; off > 0; off >>= 1) {
        if (s < off) sh[s] += sh[s + off];
        __syncthreads();
    }
    alpha[s * Bb + b] = e / sh[0];
}

__global__ void k_context(const float* __restrict__ enc, const float* __restrict__ alpha,
                          float* __restrict__ x, float* __restrict__ c1) {
    const int b = blockIdx.x;
    const int t = threadIdx.x; // 512
    float a0 = 0.f, a1 = 0.f, a2 = 0.f, a3 = 0.f;
    for (int s = 0; s < Ss; s++) {
        const float al = alpha[s * Bb + b];
        const float* e = enc + (size_t)(s * Bb + b) * 2048 + t;
        a0 += al * e[0];
        a1 += al * e[512];
        a2 += al * e[1024];
        a3 += al * e[1536];
    }
    x[b * 2560 + 512 + t]        = a0;  c1[b * 3584 + 1024 + t]        = a0;
    x[b * 2560 + 512 + 512 + t]  = a1;  c1[b * 3584 + 1024 + 512 + t]  = a1;
    x[b * 2560 + 512 + 1024 + t] = a2;  c1[b * 3584 + 1024 + 1024 + t] = a2;
    x[b * 2560 + 512 + 1536 + t] = a3;  c1[b * 3584 + 1024 + 1536 + t] = a3;
}

__global__ void k_gru(const float* __restrict__ dh, const float* __restrict__ gx,
                      const float* __restrict__ gh, float* __restrict__ hout,
                      float* __restrict__ c1) {
    const int b = blockIdx.x;
    const int h = threadIdx.x; // 1024
    const float xr = gx[b * 3072 + h],        hr = gh[b * 3072 + h];
    const float xz = gx[b * 3072 + 1024 + h], hz = gh[b * 3072 + 1024 + h];
    const float xn = gx[b * 3072 + 2048 + h], hn = gh[b * 3072 + 2048 + h];
    const float rg = 1.f / (1.f + __expf(-(xr + hr)));
    const float zg = 1.f / (1.f + __expf(-(xz + hz)));
    const float ng = tanh_fast(xn + rg * hn);
    const float hv = (1.f - zg) * ng + zg * dh[b * Hh + h];
    hout[b * Hh + h] = hv;
    c1[b * 3584 + h] = hv;
}

// ---------------- launch ----------------------------------------------------
extern "C" void kernel_launch(void* const* d_in, const int* in_sizes, int n_in,
                              void* d_out, int out_size) {
    const int*   tl   = (const int*)d_in[0];
    const float* dh   = (const float*)d_in[1];
    const float* enc  = (const float*)d_in[2];
    const float* emb  = (const float*)d_in[3];
    const float* W1   = (const float*)d_in[4];
    const float* b1   = (const float*)d_in[5];
    const float* W2   = (const float*)d_in[6];
    // d_in[7] = b2 (softmax-invariant, skipped)
    const float* Wih  = (const float*)d_in[8];
    const float* Whh  = (const float*)d_in[9];
    const float* bih  = (const float*)d_in[10];
    const float* bhh  = (const float*)d_in[11];
    const float* Wout = (const float*)d_in[12];
    const float* bout = (const float*)d_in[13];

    float* pred = (float*)d_out;                 // [128, 32000]
    float* hout = pred + (size_t)Bb * Vv;        // [128, 1024]

    float *x, *c1, *hb, *part, *alpha, *gx, *gh;
    cudaGetSymbolAddress((void**)&x,     g_x);
    cudaGetSymbolAddress((void**)&c1,    g_c1);
    cudaGetSymbolAddress((void**)&hb,    g_hb);
    cudaGetSymbolAddress((void**)&part,  g_part);
    cudaGetSymbolAddress((void**)&alpha, g_alpha);
    cudaGetSymbolAddress((void**)&gx,    g_gx);
    cudaGetSymbolAddress((void**)&gh,    g_gh);

    cudaFuncSetAttribute(gemm_h<0>, cudaFuncAttributeMaxDynamicSharedMemorySize, DSMEM_BYTES);
    cudaFuncSetAttribute(gemm_h<1>, cudaFuncAttributeMaxDynamicSharedMemorySize, DSMEM_BYTES);

    // 1) embeddings -> x[:, :512], c1[:, 3072:]
    k_embed<<<Bb, 512>>>(tl, emb, x, c1);

    // 2) hb = dh @ W1[:, 2048:3072]^T + b1   (M=128, N=1024, K=1024)
    gemm_h<0><<<dim3(8, 1), 128, DSMEM_BYTES>>>(dh, W1 + 2048, b1, hb,
                                                Bb, Hh, Hh, 3 * Hh, Hh,
                                                nullptr, nullptr);

    // 3) energy GEMM + fused tanh*W2 reduction (M=16384, N=1024, K=2048)
    gemm_h<1><<<dim3(8, 128), 128, DSMEM_BYTES>>>(enc, W1, nullptr, part,
                                                  Ss * Bb, 2 * Hh, 2 * Hh, 3 * Hh, 0,
                                                  hb, W2);

    // 4) combine partials + softmax over s  -> alpha[s][b]
    k_softmax<<<Bb, Ss>>>(part, alpha);

    // 5) context a = sum_s alpha * enc -> x[:, 512:], c1[:, 1024:3072]
    k_context<<<Bb, 512>>>(enc, alpha, x, c1);

    // 6) gx = x @ Wih^T + bih   (M=128, N=3072, K=2560)
    gemm_h<0><<<dim3(24, 1), 128, DSMEM_BYTES>>>(x, Wih, bih, gx,
                                                 Bb, 2560, 2560, 2560, 3 * Hh,
                                                 nullptr, nullptr);

    // 7) gh = dh @ Whh^T + bhh  (M=128, N=3072, K=1024)
    gemm_h<0><<<dim3(24, 1), 128, DSMEM_BYTES>>>(dh, Whh, bhh, gh,
                                                 Bb, Hh, Hh, Hh, 3 * Hh,
                                                 nullptr, nullptr);

    // 8) GRU elementwise -> h_new (output tail) and c1[:, :1024]
    k_gru<<<Bb, Hh>>>(dh, gx, gh, hout, c1);

    // 9) pred = c1 @ Wout^T + bout  (M=128, N=32000, K=3584)
    gemm_h<0><<<dim3(250, 1), 128, DSMEM_BYTES>>>(c1, Wout, bout, pred,
                                                  Bb, 3584, 3584, 3584, Vv,
                                                  nullptr, nullptr);
}

// round 7
// speedup vs baseline: 1.6759x; 1.2642x over previous
#include <cuda_runtime.h>
#include <cuda_fp16.h>
#include <cstdint>

// Problem constants
#define Bb 128
#define Ss 128
#define Hh 1024
#define Ee 512
#define Vv 32000

// fp16 GEMM tile config: CTA 128x128, 4 warps, warp tile 64x64, BK=32, 3 stages
#define BM 128
#define BN 128
#define BK 32
#define SAH 40                       // padded smem row stride in halfs (80B rows)
#define TILE_H (BM * SAH)            // 5120 halfs per A or B tile
#define STAGE_H (2 * TILE_H)         // 10240 halfs per stage
#define NSTG 3
#define DSMEM_BYTES (NSTG * STAGE_H * 2)   // 61440

// ---------------- scratch (device globals; no allocation allowed) ----------
__device__ __align__(256) __half g_ench[(size_t)Ss * Bb * 2 * Hh]; // enc fp16
__device__ __align__(256) __half g_w1e[Hh * 2 * Hh];               // W1[:, :2048] fp16
__device__ __align__(256) __half g_dhh[Bb * Hh];                   // dh fp16
__device__ __align__(256) __half g_xh[Bb * 2560];                  // [embeds | a] fp16
__device__ __align__(256) __half g_c1h[Bb * 3584];                 // [h | a | emb] fp16
__device__ __align__(256) float  g_hb[Bb * Hh];
__device__ __align__(256) float  g_part[8 * Ss * Bb];
__device__ __align__(256) float  g_alpha[Ss * Bb];
__device__ __align__(256) float  g_gx[Bb * 3 * Hh];
__device__ __align__(256) float  g_gh[Bb * 3 * Hh];

// ---------------- helpers ---------------------------------------------------
__device__ __forceinline__ uint32_t smem_u32(const void* p) {
    uint32_t a;
    asm("{ .reg .u64 t; cvta.to.shared.u64 t, %1; cvt.u32.u64 %0, t; }"
        : "=r"(a) : "l"(p));
    return a;
}

__device__ __forceinline__ void mma_f16(float* c,
                                        uint32_t a0, uint32_t a1, uint32_t a2, uint32_t a3,
                                        uint32_t b0, uint32_t b1) {
    asm volatile(
        "mma.sync.aligned.m16n8k16.row.col.f32.f16.f16.f32 "
        "{%0,%1,%2,%3}, {%4,%5,%6,%7}, {%8,%9}, {%0,%1,%2,%3};"
        : "+f"(c[0]), "+f"(c[1]), "+f"(c[2]), "+f"(c[3])
        : "r"(a0), "r"(a1), "r"(a2), "r"(a3), "r"(b0), "r"(b1));
}

__device__ __forceinline__ void ldsm4(uint32_t& r0, uint32_t& r1,
                                      uint32_t& r2, uint32_t& r3, uint32_t addr) {
    asm volatile("ldmatrix.sync.aligned.m8n8.x4.shared.b16 {%0,%1,%2,%3}, [%4];"
                 : "=r"(r0), "=r"(r1), "=r"(r2), "=r"(r3) : "r"(addr));
}

__device__ __forceinline__ void cp16u(uint32_t dst, const void* src) {
    asm volatile("cp.async.ca.shared.global [%0], [%1], 16;" :: "r"(dst), "l"(src));
}
__device__ __forceinline__ void cp_commit() {
    asm volatile("cp.async.commit_group;" ::: "memory");
}
template <int N>
__device__ __forceinline__ void cp_wait() {
    asm volatile("cp.async.wait_group %0;" :: "n"(N) : "memory");
}

__device__ __forceinline__ float tanh_fast(float x) {
    x = fminf(10.f, fmaxf(-10.f, x));
    const float t = __expf(2.f * x);
    return (t - 1.f) / (t + 1.f);
}

__device__ __forceinline__ uint2 cvt_f4_h4(float4 v) {
    half2 h0 = __floats2half2_rn(v.x, v.y);
    half2 h1 = __floats2half2_rn(v.z, v.w);
    uint2 u;
    u.x = *reinterpret_cast<uint32_t*>(&h0);
    u.y = *reinterpret_cast<uint32_t*>(&h1);
    return u;
}

// ---------------- GEMM compute body: ldmatrix + m16n8k16 --------------------
__device__ __forceinline__ void compute_kb(uint32_t aBase, uint32_t bBase,
                                           float c[4][8][4], int wm, int wn,
                                           uint32_t aOff, uint32_t bOff) {
#pragma unroll
    for (int ks = 0; ks < 2; ks++) {
        const uint32_t k0b = ks * 32;   // 16 halfs
        uint32_t af[4][4], bf[4][4];
#pragma unroll
        for (int mf = 0; mf < 4; mf++)
            ldsm4(af[mf][0], af[mf][1], af[mf][2], af[mf][3],
                  aBase + (uint32_t)(((wm * 64 + mf * 16) * SAH) * 2) + k0b + aOff);
#pragma unroll
        for (int np = 0; np < 4; np++)
            ldsm4(bf[np][0], bf[np][1], bf[np][2], bf[np][3],
                  bBase + (uint32_t)(((wn * 64 + np * 16) * SAH) * 2) + k0b + bOff);
#pragma unroll
        for (int nf = 0; nf < 8; nf++) {
            const uint32_t b0 = bf[nf >> 1][(nf & 1) << 1];
            const uint32_t b1 = bf[nf >> 1][((nf & 1) << 1) + 1];
#pragma unroll
            for (int mf = 0; mf < 4; mf++)
                mma_f16(c[mf][nf], af[mf][0], af[mf][1], af[mf][2], af[mf][3], b0, b1);
        }
    }
}

// ---------------- shared epilogues ------------------------------------------
template <int EPI>
__device__ __forceinline__ void epilogue(float c[4][8][4],
                                         const float* __restrict__ bias,
                                         float* __restrict__ out,
                                         int M, int ldc, int m0, int n0,
                                         const float* __restrict__ hb,
                                         const float* __restrict__ W2,
                                         float (*red)[2],
                                         int tid, int wm, int wn, int r, int q,
                                         int bx) {
    if (EPI == 0) {
#pragma unroll
        for (int mf = 0; mf < 4; mf++)
#pragma unroll
            for (int rr = 0; rr < 2; rr++) {
                const int mg = m0 + wm * 64 + mf * 16 + rr * 8 + r;
#pragma unroll
                for (int nf = 0; nf < 8; nf++) {
                    const int ng = n0 + wn * 64 + nf * 8 + q * 2;
                    float2 v;
                    v.x = c[mf][nf][rr * 2 + 0] + bias[ng];
                    v.y = c[mf][nf][rr * 2 + 1] + bias[ng + 1];
                    *(float2*)&out[(size_t)mg * ldc + ng] = v;
                }
            }
    } else {
        float rs[4][2];
#pragma unroll
        for (int mf = 0; mf < 4; mf++)
#pragma unroll
            for (int rr = 0; rr < 2; rr++) {
                const int row = wm * 64 + mf * 16 + rr * 8 + r; // == b
                float acc = 0.f;
#pragma unroll
                for (int nf = 0; nf < 8; nf++) {
                    const int ng = n0 + wn * 64 + nf * 8 + q * 2;
                    const float h0 = hb[row * Hh + ng];
                    const float h1 = hb[row * Hh + ng + 1];
                    acc += tanh_fast(c[mf][nf][rr * 2 + 0] + h0) * W2[ng];
                    acc += tanh_fast(c[mf][nf][rr * 2 + 1] + h1) * W2[ng + 1];
                }
                rs[mf][rr] = acc;
            }
#pragma unroll
        for (int mf = 0; mf < 4; mf++)
#pragma unroll
            for (int rr = 0; rr < 2; rr++) {
                rs[mf][rr] += __shfl_xor_sync(0xffffffffu, rs[mf][rr], 1);
                rs[mf][rr] += __shfl_xor_sync(0xffffffffu, rs[mf][rr], 2);
            }
        if (q == 0) {
#pragma unroll
            for (int mf = 0; mf < 4; mf++)
#pragma unroll
                for (int rr = 0; rr < 2; rr++)
                    red[wm * 64 + mf * 16 + rr * 8 + r][wn] = rs[mf][rr];
        }
        __syncthreads();
        if (tid < BM)
            out[(size_t)bx * M + m0 + tid] = red[tid][0] + red[tid][1];
    }
}

// ============================================================================
// HH: A fp16, B fp16 — both sides cp.async. (energy GEMM)
// ============================================================================
template <int EPI>
__global__ __launch_bounds__(128, 2)
void gemm_hh(const __half* __restrict__ A, const __half* __restrict__ Bw,
             const float* __restrict__ bias, float* __restrict__ out,
             int M, int K, int lda, int ldb, int ldc,
             const float* __restrict__ hb, const float* __restrict__ W2) {
    extern __shared__ __align__(16) __half dynh[];
    __shared__ float red[BM][2];

    const int tid = threadIdx.x, lane = tid & 31, wid = tid >> 5;
    const int wm = wid >> 1, wn = wid & 1, r = lane >> 2, q = lane & 3;
    const int m0 = blockIdx.y * BM, n0 = blockIdx.x * BN;
    const int nK = K / BK;
    const uint32_t dynU = smem_u32(dynh);
    const uint32_t aOff = (uint32_t)((((lane & 15) * SAH) + (lane >> 4) * 8) * 2);
    const uint32_t bOff = (uint32_t)(((((lane >> 4) * 8 + (lane & 7)) * SAH)
                                      + ((lane >> 3) & 1) * 8) * 2);

    float c[4][8][4];
#pragma unroll
    for (int i = 0; i < 4; i++)
#pragma unroll
        for (int j = 0; j < 8; j++)
#pragma unroll
            for (int k = 0; k < 4; k++) c[i][j][k] = 0.f;

    auto cpfill = [&](int kb, int stg) {
        const uint32_t base = dynU + stg * (STAGE_H * 2);
        const int ko = kb * BK;
#pragma unroll
        for (int h = 0; h < 4; h++) {
            const int cc = tid + h * 128;
            const int row = cc >> 2, g = cc & 3;
            cp16u(base + (row * SAH + g * 8) * 2,
                  A + (size_t)(m0 + row) * lda + ko + g * 8);
            cp16u(base + TILE_H * 2 + (row * SAH + g * 8) * 2,
                  Bw + (size_t)(n0 + row) * ldb + ko + g * 8);
        }
    };

    cpfill(0, 0); cp_commit();
    cpfill(1, 1); cp_commit();
    cp_wait<1>(); __syncthreads();

    int stg = 0;
    for (int kb = 0; kb < nK; kb++) {
        if (kb + 2 < nK) {
            int s2 = stg + 2; if (s2 >= NSTG) s2 -= NSTG;
            cpfill(kb + 2, s2);
        }
        cp_commit();
        const uint32_t aB = dynU + stg * (STAGE_H * 2);
        compute_kb(aB, aB + TILE_H * 2, c, wm, wn, aOff, bOff);
        cp_wait<1>(); __syncthreads();
        if (++stg == NSTG) stg = 0;
    }
    epilogue<EPI>(c, bias, out, M, ldc, m0, n0, hb, W2, red, tid, wm, wn, r, q,
                  blockIdx.x);
}

// ============================================================================
// HF: A fp16 (cp.async), B fp32 (LDG -> cvt -> STS). (hb, gx, gh, pred)
// ============================================================================
template <int EPI>
__global__ __launch_bounds__(128, 2)
void gemm_hf(const __half* __restrict__ A, const float* __restrict__ Bw,
             const float* __restrict__ bias, float* __restrict__ out,
             int M, int K, int lda, int ldb, int ldc,
             const float* __restrict__ hb, const float* __restrict__ W2) {
    extern __shared__ __align__(16) __half dynh[];
    __shared__ float red[BM][2];

    const int tid = threadIdx.x, lane = tid & 31, wid = tid >> 5;
    const int wm = wid >> 1, wn = wid & 1, r = lane >> 2, q = lane & 3;
    const int m0 = blockIdx.y * BM, n0 = blockIdx.x * BN;
    const int nK = K / BK;
    const uint32_t dynU = smem_u32(dynh);
    const uint32_t aOff = (uint32_t)((((lane & 15) * SAH) + (lane >> 4) * 8) * 2);
    const uint32_t bOff = (uint32_t)(((((lane >> 4) * 8 + (lane & 7)) * SAH)
                                      + ((lane >> 3) & 1) * 8) * 2);

    int rowv[8], gv[8];
#pragma unroll
    for (int h = 0; h < 8; h++) {
        const int idx = tid + h * 128;
        rowv[h] = idx >> 3;
        gv[h]   = idx & 7;
    }

    float c[4][8][4];
#pragma unroll
    for (int i = 0; i < 4; i++)
#pragma unroll
        for (int j = 0; j < 8; j++)
#pragma unroll
            for (int k = 0; k < 4; k++) c[i][j][k] = 0.f;

    uint2 sb[8];
    auto cpA = [&](int kb, int stg) {
        const uint32_t base = dynU + stg * (STAGE_H * 2);
        const int ko = kb * BK;
#pragma unroll
        for (int h = 0; h < 4; h++) {
            const int cc = tid + h * 128;
            const int row = cc >> 2, g = cc & 3;
            cp16u(base + (row * SAH + g * 8) * 2,
                  A + (size_t)(m0 + row) * lda + ko + g * 8);
        }
    };
    auto ldB = [&](int kb) {
        const int ko = kb * BK;
#pragma unroll
        for (int h = 0; h < 8; h++)
            sb[h] = cvt_f4_h4(*(const float4*)(Bw + (size_t)(n0 + rowv[h]) * ldb
                                               + ko + gv[h] * 4));
    };
    auto stsB = [&](int stg) {
        __half* D = dynh + stg * STAGE_H + TILE_H;
#pragma unroll
        for (int h = 0; h < 8; h++)
            *(uint2*)(D + rowv[h] * SAH + gv[h] * 4) = sb[h];
    };

    cpA(0, 0); cp_commit();
    cpA(1, 1); cp_commit();
    ldB(0); stsB(0); ldB(1);
    cp_wait<1>(); __syncthreads();

    int stg = 0;
    for (int kb = 0; kb < nK; kb++) {
        int w = stg + 1; if (w == NSTG) w = 0;
        if (kb + 1 < nK) stsB(w);                // regs hold B(kb+1)
        if (kb + 2 < nK) {
            int s2 = stg + 2; if (s2 >= NSTG) s2 -= NSTG;
            cpA(kb + 2, s2);
            ldB(kb + 2);
        }
        cp_commit();
        const uint32_t aB = dynU + stg * (STAGE_H * 2);
        compute_kb(aB, aB + TILE_H * 2, c, wm, wn, aOff, bOff);
        cp_wait<1>(); __syncthreads();
        stg = w;
    }
    epilogue<EPI>(c, bias, out, M, ldc, m0, n0, hb, W2, red, tid, wm, wn, r, q,
                  blockIdx.x);
}

// ---------------- conversion + small kernels ---------------------------------
__global__ void k_cvt4(const float4* __restrict__ src, uint2* __restrict__ dst, int n4) {
    const int i = blockIdx.x * blockDim.x + threadIdx.x;
    if (i < n4) dst[i] = cvt_f4_h4(src[i]);
}

__global__ void k_cvt_w1e(const float* __restrict__ W1, __half* __restrict__ dst) {
    const int i = blockIdx.x * 256 + threadIdx.x;   // 0..524287
    const int row = i >> 9, c4 = i & 511;
    float4 v = *(const float4*)(W1 + (size_t)row * 3072 + c4 * 4);
    *(uint2*)(dst + row * 2048 + c4 * 4) = cvt_f4_h4(v);
}

__global__ void k_embed(const int* __restrict__ tl, const float* __restrict__ emb,
                        __half* __restrict__ xh, __half* __restrict__ c1h) {
    const int b = blockIdx.x;
    const int e = threadIdx.x; // 512
    const __half v = __float2half_rn(emb[(size_t)tl[b] * Ee + e]);
    xh[b * 2560 + e] = v;
    c1h[b * 3584 + 3072 + e] = v;
}

__global__ void k_softmax(const float* __restrict__ part, float* __restrict__ alpha) {
    const int b = blockIdx.x;
    const int s = threadIdx.x; // 128
    float sc = 0.f;
#pragma unroll
    for (int p = 0; p < 8; p++) sc += part[p * (Ss * Bb) + s * Bb + b];
    __shared__ float sh[Ss];
    sh[s] = sc; __syncthreads();
    for (int off = 64; off > 0; off >>= 1) {
        if (s < off) sh[s] = fmaxf(sh[s], sh[s + off]);
        __syncthreads();
    }
    const float mx = sh[0]; __syncthreads();
    const float e = __expf(sc - mx);
    sh[s] = e; __syncthreads();
    for (int off = 64; off > 0; off >>= 1) {
        if (s < off) sh[s] += sh[s + off];
        __syncthreads();
    }
    alpha[s * Bb + b] = e / sh[0];
}

__global__ void k_context(const float* __restrict__ enc, const float* __restrict__ alpha,
                          __half* __restrict__ xh, __half* __restrict__ c1h) {
    const int b = blockIdx.x;
    const int t = threadIdx.x; // 512
    float a0 = 0.f, a1 = 0.f, a2 = 0.f, a3 = 0.f;
    for (int s = 0; s < Ss; s++) {
        const float al = alpha[s * Bb + b];
        const float* e = enc + (size_t)(s * Bb + b) * 2048 + t;
        a0 += al * e[0];
        a1 += al * e[512];
        a2 += al * e[1024];
        a3 += al * e[1536];
    }
    const __half h0 = __float2half_rn(a0), h1 = __float2half_rn(a1);
    const __half h2 = __float2half_rn(a2), h3 = __float2half_rn(a3);
    xh[b * 2560 + 512 + t]         = h0;  c1h[b * 3584 + 1024 + t]        = h0;
    xh[b * 2560 + 512 + 512 + t]   = h1;  c1h[b * 3584 + 1024 + 512 + t]  = h1;
    xh[b * 2560 + 512 + 1024 + t]  = h2;  c1h[b * 3584 + 1024 + 1024 + t] = h2;
    xh[b * 2560 + 512 + 1536 + t]  = h3;  c1h[b * 3584 + 1024 + 1536 + t] = h3;
}

__global__ void k_gru(const float* __restrict__ dh, const float* __restrict__ gx,
                      const float* __restrict__ gh, float* __restrict__ hout,
                      __half* __restrict__ c1h) {
    const int b = blockIdx.x;
    const int h = threadIdx.x; // 1024
    const float xr = gx[b * 3072 + h],        hr = gh[b * 3072 + h];
    const float xz = gx[b * 3072 + 1024 + h], hz = gh[b * 3072 + 1024 + h];
    const float xn = gx[b * 3072 + 2048 + h], hn = gh[b * 3072 + 2048 + h];
    const float rg = 1.f / (1.f + __expf(-(xr + hr)));
    const float zg = 1.f / (1.f + __expf(-(xz + hz)));
    const float ng = tanh_fast(xn + rg * hn);
    const float hv = (1.f - zg) * ng + zg * dh[b * Hh + h];
    hout[b * Hh + h] = hv;
    c1h[b * 3584 + h] = __float2half_rn(hv);
}

// ---------------- launch ----------------------------------------------------
extern "C" void kernel_launch(void* const* d_in, const int* in_sizes, int n_in,
                              void* d_out, int out_size) {
    const int*   tl   = (const int*)d_in[0];
    const float* dh   = (const float*)d_in[1];
    const float* enc  = (const float*)d_in[2];
    const float* emb  = (const float*)d_in[3];
    const float* W1   = (const float*)d_in[4];
    const float* b1   = (const float*)d_in[5];
    const float* W2   = (const float*)d_in[6];
    // d_in[7] = b2 (softmax-invariant, skipped)
    const float* Wih  = (const float*)d_in[8];
    const float* Whh  = (const float*)d_in[9];
    const float* bih  = (const float*)d_in[10];
    const float* bhh  = (const float*)d_in[11];
    const float* Wout = (const float*)d_in[12];
    const float* bout = (const float*)d_in[13];

    float* pred = (float*)d_out;                 // [128, 32000]
    float* hout = pred + (size_t)Bb * Vv;        // [128, 1024]

    __half *ench, *w1e, *dhh, *xh, *c1h;
    float *hbp, *part, *alpha, *gx, *gh;
    cudaGetSymbolAddress((void**)&ench,  g_ench);
    cudaGetSymbolAddress((void**)&w1e,   g_w1e);
    cudaGetSymbolAddress((void**)&dhh,   g_dhh);
    cudaGetSymbolAddress((void**)&xh,    g_xh);
    cudaGetSymbolAddress((void**)&c1h,   g_c1h);
    cudaGetSymbolAddress((void**)&hbp,   g_hb);
    cudaGetSymbolAddress((void**)&part,  g_part);
    cudaGetSymbolAddress((void**)&alpha, g_alpha);
    cudaGetSymbolAddress((void**)&gx,    g_gx);
    cudaGetSymbolAddress((void**)&gh,    g_gh);

    cudaFuncSetAttribute(gemm_hh<1>, cudaFuncAttributeMaxDynamicSharedMemorySize, DSMEM_BYTES);
    cudaFuncSetAttribute(gemm_hf<0>, cudaFuncAttributeMaxDynamicSharedMemorySize, DSMEM_BYTES);

    // 0) conversions: enc -> fp16, W1[:, :2048] -> fp16, dh -> fp16
    k_cvt4<<<32768, 256>>>((const float4*)enc, (uint2*)ench, (Ss * Bb * 2 * Hh) / 4);
    k_cvt_w1e<<<2048, 256>>>(W1, w1e);
    k_cvt4<<<128, 256>>>((const float4*)dh, (uint2*)dhh, (Bb * Hh) / 4);

    // 1) embeddings -> xh[:, :512], c1h[:, 3072:]
    k_embed<<<Bb, 512>>>(tl, emb, xh, c1h);

    // 2) hb = dh @ W1[:, 2048:3072]^T + b1   (M=128, N=1024, K=1024)
    gemm_hf<0><<<dim3(8, 1), 128, DSMEM_BYTES>>>(dhh, W1 + 2048, b1, hbp,
                                                 Bb, Hh, Hh, 3 * Hh, Hh,
                                                 nullptr, nullptr);

    // 3) energy GEMM + fused tanh*W2 reduction (M=16384, N=1024, K=2048)
    gemm_hh<1><<<dim3(8, 128), 128, DSMEM_BYTES>>>(ench, w1e, nullptr, part,
                                                   Ss * Bb, 2 * Hh, 2 * Hh, 2 * Hh, 0,
                                                   hbp, W2);

    // 4) combine partials + softmax over s  -> alpha[s][b]
    k_softmax<<<Bb, Ss>>>(part, alpha);

    // 5) context a -> xh[:, 512:], c1h[:, 1024:3072]
    k_context<<<Bb, 512>>>(enc, alpha, xh, c1h);

    // 6) gx = x @ Wih^T + bih   (M=128, N=3072, K=2560)
    gemm_hf<0><<<dim3(24, 1), 128, DSMEM_BYTES>>>(xh, Wih, bih, gx,
                                                  Bb, 2560, 2560, 2560, 3 * Hh,
                                                  nullptr, nullptr);

    // 7) gh = dh @ Whh^T + bhh  (M=128, N=3072, K=1024)
    gemm_hf<0><<<dim3(24, 1), 128, DSMEM_BYTES>>>(dhh, Whh, bhh, gh,
                                                  Bb, Hh, Hh, Hh, 3 * Hh,
                                                  nullptr, nullptr);

    // 8) GRU elementwise -> h_new (output tail, fp32) and c1h[:, :1024]
    k_gru<<<Bb, Hh>>>(dh, gx, gh, hout, c1h);

    // 9) pred = c1 @ Wout^T + bout  (M=128, N=32000, K=3584)
    gemm_hf<0><<<dim3(250, 1), 128, DSMEM_BYTES>>>(c1h, Wout, bout, pred,
                                                   Bb, 3584, 3584, 3584, Vv,
                                                   nullptr, nullptr);
}

// round 8
// speedup vs baseline: 2.0763x; 1.2389x over previous
#include <cuda_runtime.h>
#include <cuda_fp16.h>
#include <cstdint>

// Problem constants
#define Bb 128
#define Ss 128
#define Hh 1024
#define Ee 512
#define Vv 32000

// fp16 GEMM tile config: CTA 128x128, 4 warps, warp tile 64x64, BK=32, 3 stages
#define BM 128
#define BN 128
#define BK 32
#define SAH 40                       // padded smem row stride in halfs (80B rows)
#define TILE_H (BM * SAH)            // 5120 halfs per A or B tile
#define STAGE_H (2 * TILE_H)         // 10240 halfs per stage
#define NSTG 3
#define DSMEM_BYTES (NSTG * STAGE_H * 2)   // 61440

// ---------------- scratch (device globals; no allocation allowed) ----------
__device__ __align__(256) __half g_ench[(size_t)Ss * Bb * 2 * Hh]; // enc fp16
__device__ __align__(256) __half g_w1e[Hh * 2 * Hh];               // W1[:, :2048] fp16
__device__ __align__(256) __half g_dhh[Bb * Hh];                   // dh fp16
__device__ __align__(256) __half g_xh[Bb * 2560];                  // [embeds | a] fp16
__device__ __align__(256) __half g_c1h[Bb * 3584];                 // [h | a | emb] fp16
__device__ __align__(256) float  g_hb[Bb * Hh];
__device__ __align__(256) float  g_part[8 * Ss * Bb];
__device__ __align__(256) float  g_alpha[Ss * Bb];
__device__ __align__(256) float  g_gx[Bb * 3 * Hh];
__device__ __align__(256) float  g_gh[Bb * 3 * Hh];

// ---------------- helpers ---------------------------------------------------
__device__ __forceinline__ uint32_t smem_u32(const void* p) {
    uint32_t a;
    asm("{ .reg .u64 t; cvta.to.shared.u64 t, %1; cvt.u32.u64 %0, t; }"
        : "=r"(a) : "l"(p));
    return a;
}

__device__ __forceinline__ void mma_f16(float* c,
                                        uint32_t a0, uint32_t a1, uint32_t a2, uint32_t a3,
                                        uint32_t b0, uint32_t b1) {
    asm volatile(
        "mma.sync.aligned.m16n8k16.row.col.f32.f16.f16.f32 "
        "{%0,%1,%2,%3}, {%4,%5,%6,%7}, {%8,%9}, {%0,%1,%2,%3};"
        : "+f"(c[0]), "+f"(c[1]), "+f"(c[2]), "+f"(c[3])
        : "r"(a0), "r"(a1), "r"(a2), "r"(a3), "r"(b0), "r"(b1));
}

__device__ __forceinline__ void ldsm4(uint32_t& r0, uint32_t& r1,
                                      uint32_t& r2, uint32_t& r3, uint32_t addr) {
    asm volatile("ldmatrix.sync.aligned.m8n8.x4.shared.b16 {%0,%1,%2,%3}, [%4];"
                 : "=r"(r0), "=r"(r1), "=r"(r2), "=r"(r3) : "r"(addr));
}

__device__ __forceinline__ void cp16u(uint32_t dst, const void* src) {
    asm volatile("cp.async.ca.shared.global [%0], [%1], 16;" :: "r"(dst), "l"(src));
}
__device__ __forceinline__ void cp_commit() {
    asm volatile("cp.async.commit_group;" ::: "memory");
}
template <int N>
__device__ __forceinline__ void cp_wait() {
    asm volatile("cp.async.wait_group %0;" :: "n"(N) : "memory");
}

__device__ __forceinline__ float tanh_fast(float x) {
    x = fminf(10.f, fmaxf(-10.f, x));
    const float t = __expf(2.f * x);
    return (t - 1.f) / (t + 1.f);
}

__device__ __forceinline__ uint2 cvt_f4_h4(float4 v) {
    half2 h0 = __floats2half2_rn(v.x, v.y);
    half2 h1 = __floats2half2_rn(v.z, v.w);
    uint2 u;
    u.x = *reinterpret_cast<uint32_t*>(&h0);
    u.y = *reinterpret_cast<uint32_t*>(&h1);
    return u;
}

// ---------------- GEMM compute body: ldmatrix + m16n8k16 --------------------
__device__ __forceinline__ void compute_kb(uint32_t aBase, uint32_t bBase,
                                           float c[4][8][4], int wm, int wn,
                                           uint32_t aOff, uint32_t bOff) {
#pragma unroll
    for (int ks = 0; ks < 2; ks++) {
        const uint32_t k0b = ks * 32;   // 16 halfs
        uint32_t af[4][4], bf[4][4];
#pragma unroll
        for (int mf = 0; mf < 4; mf++)
            ldsm4(af[mf][0], af[mf][1], af[mf][2], af[mf][3],
                  aBase + (uint32_t)(((wm * 64 + mf * 16) * SAH) * 2) + k0b + aOff);
#pragma unroll
        for (int np = 0; np < 4; np++)
            ldsm4(bf[np][0], bf[np][1], bf[np][2], bf[np][3],
                  bBase + (uint32_t)(((wn * 64 + np * 16) * SAH) * 2) + k0b + bOff);
#pragma unroll
        for (int nf = 0; nf < 8; nf++) {
            const uint32_t b0 = bf[nf >> 1][(nf & 1) << 1];
            const uint32_t b1 = bf[nf >> 1][((nf & 1) << 1) + 1];
#pragma unroll
            for (int mf = 0; mf < 4; mf++)
                mma_f16(c[mf][nf], af[mf][0], af[mf][1], af[mf][2], af[mf][3], b0, b1);
        }
    }
}

// ---------------- epilogues --------------------------------------------------
// EPI 0: out = acc + bias   EPI 1: energy reduce   EPI 2: out += acc
template <int EPI>
__device__ __forceinline__ void epilogue(float c[4][8][4],
                                         const float* __restrict__ bias,
                                         float* __restrict__ out,
                                         int M, int ldc, int m0, int n0,
                                         const float* __restrict__ hb,
                                         const float* __restrict__ W2,
                                         float (*red)[2],
                                         int tid, int wm, int wn, int r, int q,
                                         int bx) {
    if (EPI == 0 || EPI == 2) {
#pragma unroll
        for (int mf = 0; mf < 4; mf++)
#pragma unroll
            for (int rr = 0; rr < 2; rr++) {
                const int mg = m0 + wm * 64 + mf * 16 + rr * 8 + r;
#pragma unroll
                for (int nf = 0; nf < 8; nf++) {
                    const int ng = n0 + wn * 64 + nf * 8 + q * 2;
                    float* p = &out[(size_t)mg * ldc + ng];
                    float2 v;
                    if (EPI == 0) {
                        v.x = c[mf][nf][rr * 2 + 0] + bias[ng];
                        v.y = c[mf][nf][rr * 2 + 1] + bias[ng + 1];
                    } else {
                        float2 o = *(float2*)p;
                        v.x = o.x + c[mf][nf][rr * 2 + 0];
                        v.y = o.y + c[mf][nf][rr * 2 + 1];
                    }
                    *(float2*)p = v;
                }
            }
    } else {
        float rs[4][2];
#pragma unroll
        for (int mf = 0; mf < 4; mf++)
#pragma unroll
            for (int rr = 0; rr < 2; rr++) {
                const int row = wm * 64 + mf * 16 + rr * 8 + r; // == b
                float acc = 0.f;
#pragma unroll
                for (int nf = 0; nf < 8; nf++) {
                    const int ng = n0 + wn * 64 + nf * 8 + q * 2;
                    const float h0 = hb[row * Hh + ng];
                    const float h1 = hb[row * Hh + ng + 1];
                    acc += tanh_fast(c[mf][nf][rr * 2 + 0] + h0) * W2[ng];
                    acc += tanh_fast(c[mf][nf][rr * 2 + 1] + h1) * W2[ng + 1];
                }
                rs[mf][rr] = acc;
            }
#pragma unroll
        for (int mf = 0; mf < 4; mf++)
#pragma unroll
            for (int rr = 0; rr < 2; rr++) {
                rs[mf][rr] += __shfl_xor_sync(0xffffffffu, rs[mf][rr], 1);
                rs[mf][rr] += __shfl_xor_sync(0xffffffffu, rs[mf][rr], 2);
            }
        if (q == 0) {
#pragma unroll
            for (int mf = 0; mf < 4; mf++)
#pragma unroll
                for (int rr = 0; rr < 2; rr++)
                    red[wm * 64 + mf * 16 + rr * 8 + r][wn] = rs[mf][rr];
        }
        __syncthreads();
        if (tid < BM)
            out[(size_t)bx * M + m0 + tid] = red[tid][0] + red[tid][1];
    }
}

// ---------------- mainloops (device functions, explicit m0/n0) --------------
// HH: A fp16, B fp16 (both cp.async)
__device__ __forceinline__ void mainloop_hh(const __half* __restrict__ A,
                                            const __half* __restrict__ Bw,
                                            int K, int lda, int ldb,
                                            int m0, int n0,
                                            float c[4][8][4], __half* dynh,
                                            int tid, int wm, int wn,
                                            uint32_t aOff, uint32_t bOff) {
    const int nK = K / BK;
    const uint32_t dynU = smem_u32(dynh);
    auto cpfill = [&](int kb, int stg) {
        const uint32_t base = dynU + stg * (STAGE_H * 2);
        const int ko = kb * BK;
#pragma unroll
        for (int h = 0; h < 4; h++) {
            const int cc = tid + h * 128;
            const int row = cc >> 2, g = cc & 3;
            cp16u(base + (row * SAH + g * 8) * 2,
                  A + (size_t)(m0 + row) * lda + ko + g * 8);
            cp16u(base + TILE_H * 2 + (row * SAH + g * 8) * 2,
                  Bw + (size_t)(n0 + row) * ldb + ko + g * 8);
        }
    };
    cpfill(0, 0); cp_commit();
    cpfill(1, 1); cp_commit();
    cp_wait<1>(); __syncthreads();
    int stg = 0;
    for (int kb = 0; kb < nK; kb++) {
        if (kb + 2 < nK) {
            int s2 = stg + 2; if (s2 >= NSTG) s2 -= NSTG;
            cpfill(kb + 2, s2);
        }
        cp_commit();
        const uint32_t aB = dynU + stg * (STAGE_H * 2);
        compute_kb(aB, aB + TILE_H * 2, c, wm, wn, aOff, bOff);
        cp_wait<1>(); __syncthreads();
        if (++stg == NSTG) stg = 0;
    }
}

// HF: A fp16 (cp.async), B fp32 (LDG -> cvt -> STS)
__device__ __forceinline__ void mainloop_hf(const __half* __restrict__ A,
                                            const float* __restrict__ Bw,
                                            int K, int lda, int ldb,
                                            int m0, int n0,
                                            float c[4][8][4], __half* dynh,
                                            int tid, int wm, int wn,
                                            uint32_t aOff, uint32_t bOff) {
    const int nK = K / BK;
    const uint32_t dynU = smem_u32(dynh);
    int rowv[8], gv[8];
#pragma unroll
    for (int h = 0; h < 8; h++) {
        const int idx = tid + h * 128;
        rowv[h] = idx >> 3;
        gv[h]   = idx & 7;
    }
    uint2 sb[8];
    auto cpA = [&](int kb, int stg) {
        const uint32_t base = dynU + stg * (STAGE_H * 2);
        const int ko = kb * BK;
#pragma unroll
        for (int h = 0; h < 4; h++) {
            const int cc = tid + h * 128;
            const int row = cc >> 2, g = cc & 3;
            cp16u(base + (row * SAH + g * 8) * 2,
                  A + (size_t)(m0 + row) * lda + ko + g * 8);
        }
    };
    auto ldB = [&](int kb) {
        const int ko = kb * BK;
#pragma unroll
        for (int h = 0; h < 8; h++)
            sb[h] = cvt_f4_h4(*(const float4*)(Bw + (size_t)(n0 + rowv[h]) * ldb
                                               + ko + gv[h] * 4));
    };
    auto stsB = [&](int stg) {
        __half* D = dynh + stg * STAGE_H + TILE_H;
#pragma unroll
        for (int h = 0; h < 8; h++)
            *(uint2*)(D + rowv[h] * SAH + gv[h] * 4) = sb[h];
    };
    cpA(0, 0); cp_commit();
    cpA(1, 1); cp_commit();
    ldB(0); stsB(0); ldB(1);
    cp_wait<1>(); __syncthreads();
    int stg = 0;
    for (int kb = 0; kb < nK; kb++) {
        int w = stg + 1; if (w == NSTG) w = 0;
        if (kb + 1 < nK) stsB(w);
        if (kb + 2 < nK) {
            int s2 = stg + 2; if (s2 >= NSTG) s2 -= NSTG;
            cpA(kb + 2, s2);
            ldB(kb + 2);
        }
        cp_commit();
        const uint32_t aB = dynU + stg * (STAGE_H * 2);
        compute_kb(aB, aB + TILE_H * 2, c, wm, wn, aOff, bOff);
        cp_wait<1>(); __syncthreads();
        stg = w;
    }
}

#define GEMM_PREAMBLE \
    extern __shared__ __align__(16) __half dynh[]; \
    __shared__ float red[BM][2]; \
    const int tid = threadIdx.x, lane = tid & 31, wid = tid >> 5; \
    const int wm = wid >> 1, wn = wid & 1, r = lane >> 2, q = lane & 3; \
    const uint32_t aOff = (uint32_t)((((lane & 15) * SAH) + (lane >> 4) * 8) * 2); \
    const uint32_t bOff = (uint32_t)(((((lane >> 4) * 8 + (lane & 7)) * SAH) \
                                      + ((lane >> 3) & 1) * 8) * 2); \
    float c[4][8][4]; \
    _Pragma("unroll") for (int i = 0; i < 4; i++) \
    _Pragma("unroll") for (int j = 0; j < 8; j++) \
    _Pragma("unroll") for (int k = 0; k < 4; k++) c[i][j][k] = 0.f;

// ============================================================================
// merged1: [0,1024) energy tiles (hh, EPI1) ; [1024,1274) pred-embeds (hf, EPI0)
// ============================================================================
__global__ __launch_bounds__(128, 2)
void k_merged1(const __half* __restrict__ ench, const __half* __restrict__ w1e,
               const float* __restrict__ hb, const float* __restrict__ W2,
               float* __restrict__ part,
               const __half* __restrict__ c1h, const float* __restrict__ Wout,
               const float* __restrict__ bout, float* __restrict__ pred) {
    GEMM_PREAMBLE
    const int bid = blockIdx.x;
    if (bid < 1024) {
        const int n0 = (bid & 7) * BN, m0 = (bid >> 3) * BM;
        mainloop_hh(ench, w1e, 2 * Hh, 2 * Hh, 2 * Hh, m0, n0,
                    c, dynh, tid, wm, wn, aOff, bOff);
        epilogue<1>(c, nullptr, part, Ss * Bb, 0, m0, n0, hb, W2, red,
                    tid, wm, wn, r, q, bid & 7);
    } else {
        const int n0 = (bid - 1024) * BN;
        mainloop_hf(c1h + 3072, Wout + 3072, Ee, 3584, 3584, 0, n0,
                    c, dynh, tid, wm, wn, aOff, bOff);
        epilogue<0>(c, bout, pred, Bb, Vv, 0, n0, nullptr, nullptr, red,
                    tid, wm, wn, r, q, 0);
    }
}

// ============================================================================
// merged2: [0,24) gx ; [24,48) gh ; [48,298) pred-a (EPI2 add)
// ============================================================================
__global__ __launch_bounds__(128, 2)
void k_merged2(const __half* __restrict__ xh, const float* __restrict__ Wih,
               const float* __restrict__ bih, float* __restrict__ gx,
               const __half* __restrict__ dhh, const float* __restrict__ Whh,
               const float* __restrict__ bhh, float* __restrict__ gh,
               const __half* __restrict__ c1h, const float* __restrict__ Wout,
               float* __restrict__ pred) {
    GEMM_PREAMBLE
    const int bid = blockIdx.x;
    if (bid < 24) {
        const int n0 = bid * BN;
        mainloop_hf(xh, Wih, 2560, 2560, 2560, 0, n0,
                    c, dynh, tid, wm, wn, aOff, bOff);
        epilogue<0>(c, bih, gx, Bb, 3 * Hh, 0, n0, nullptr, nullptr, red,
                    tid, wm, wn, r, q, 0);
    } else if (bid < 48) {
        const int n0 = (bid - 24) * BN;
        mainloop_hf(dhh, Whh, Hh, Hh, Hh, 0, n0,
                    c, dynh, tid, wm, wn, aOff, bOff);
        epilogue<0>(c, bhh, gh, Bb, 3 * Hh, 0, n0, nullptr, nullptr, red,
                    tid, wm, wn, r, q, 0);
    } else {
        const int n0 = (bid - 48) * BN;
        mainloop_hf(c1h + 1024, Wout + 1024, 2 * Hh, 3584, 3584, 0, n0,
                    c, dynh, tid, wm, wn, aOff, bOff);
        epilogue<2>(c, nullptr, pred, Bb, Vv, 0, n0, nullptr, nullptr, red,
                    tid, wm, wn, r, q, 0);
    }
}

// ============================================================================
// standalone hf GEMM (hb and pred-hnew)
// ============================================================================
template <int EPI>
__global__ __launch_bounds__(128, 2)
void gemm_hf(const __half* __restrict__ A, const float* __restrict__ Bw,
             const float* __restrict__ bias, float* __restrict__ out,
             int M, int K, int lda, int ldb, int ldc,
             const float* __restrict__ hb, const float* __restrict__ W2) {
    GEMM_PREAMBLE
    const int m0 = blockIdx.y * BM, n0 = blockIdx.x * BN;
    mainloop_hf(A, Bw, K, lda, ldb, m0, n0, c, dynh, tid, wm, wn, aOff, bOff);
    epilogue<EPI>(c, bias, out, M, ldc, m0, n0, hb, W2, red, tid, wm, wn, r, q,
                  blockIdx.x);
}

// ---------------- conversion + small kernels ---------------------------------
__global__ void k_cvt4(const float4* __restrict__ src, uint2* __restrict__ dst, int n4) {
    const int i = blockIdx.x * blockDim.x + threadIdx.x;
    if (i < n4) dst[i] = cvt_f4_h4(src[i]);
}

__global__ void k_cvt_w1e(const float* __restrict__ W1, __half* __restrict__ dst) {
    const int i = blockIdx.x * 256 + threadIdx.x;   // 0..524287
    const int row = i >> 9, c4 = i & 511;
    float4 v = *(const float4*)(W1 + (size_t)row * 3072 + c4 * 4);
    *(uint2*)(dst + row * 2048 + c4 * 4) = cvt_f4_h4(v);
}

__global__ void k_embed(const int* __restrict__ tl, const float* __restrict__ emb,
                        __half* __restrict__ xh, __half* __restrict__ c1h) {
    const int b = blockIdx.x;
    const int e = threadIdx.x; // 512
    const __half v = __float2half_rn(emb[(size_t)tl[b] * Ee + e]);
    xh[b * 2560 + e] = v;
    c1h[b * 3584 + 3072 + e] = v;
}

__global__ void k_softmax(const float* __restrict__ part, float* __restrict__ alpha) {
    const int b = blockIdx.x;
    const int s = threadIdx.x; // 128
    float sc = 0.f;
#pragma unroll
    for (int p = 0; p < 8; p++) sc += part[p * (Ss * Bb) + s * Bb + b];
    __shared__ float sh[Ss];
    sh[s] = sc; __syncthreads();
    for (int off = 64; off > 0; off >>= 1) {
        if (s < off) sh[s] = fmaxf(sh[s], sh[s + off]);
        __syncthreads();
    }
    const float mx = sh[0]; __syncthreads();
    const float e = __expf(sc - mx);
    sh[s] = e; __syncthreads();
    for (int off = 64; off > 0; off >>= 1) {
        if (s < off) sh[s] += sh[s + off];
        __syncthreads();
    }
    alpha[s * Bb + b] = e / sh[0];
}

__global__ void k_context(const float* __restrict__ enc, const float* __restrict__ alpha,
                          __half* __restrict__ xh, __half* __restrict__ c1h) {
    const int b = blockIdx.x;
    const int t = threadIdx.x; // 512
    float a0 = 0.f, a1 = 0.f, a2 = 0.f, a3 = 0.f;
    for (int s = 0; s < Ss; s++) {
        const float al = alpha[s * Bb + b];
        const float* e = enc + (size_t)(s * Bb + b) * 2048 + t;
        a0 += al * e[0];
        a1 += al * e[512];
        a2 += al * e[1024];
        a3 += al * e[1536];
    }
    const __half h0 = __float2half_rn(a0), h1 = __float2half_rn(a1);
    const __half h2 = __float2half_rn(a2), h3 = __float2half_rn(a3);
    xh[b * 2560 + 512 + t]         = h0;  c1h[b * 3584 + 1024 + t]        = h0;
    xh[b * 2560 + 512 + 512 + t]   = h1;  c1h[b * 3584 + 1024 + 512 + t]  = h1;
    xh[b * 2560 + 512 + 1024 + t]  = h2;  c1h[b * 3584 + 1024 + 1024 + t] = h2;
    xh[b * 2560 + 512 + 1536 + t]  = h3;  c1h[b * 3584 + 1024 + 1536 + t] = h3;
}

__global__ void k_gru(const float* __restrict__ dh, const float* __restrict__ gx,
                      const float* __restrict__ gh, float* __restrict__ hout,
                      __half* __restrict__ c1h) {
    const int b = blockIdx.x;
    const int h = threadIdx.x; // 1024
    const float xr = gx[b * 3072 + h],        hr = gh[b * 3072 + h];
    const float xz = gx[b * 3072 + 1024 + h], hz = gh[b * 3072 + 1024 + h];
    const float xn = gx[b * 3072 + 2048 + h], hn = gh[b * 3072 + 2048 + h];
    const float rg = 1.f / (1.f + __expf(-(xr + hr)));
    const float zg = 1.f / (1.f + __expf(-(xz + hz)));
    const float ng = tanh_fast(xn + rg * hn);
    const float hv = (1.f - zg) * ng + zg * dh[b * Hh + h];
    hout[b * Hh + h] = hv;
    c1h[b * 3584 + h] = __float2half_rn(hv);
}

// ---------------- launch ----------------------------------------------------
extern "C" void kernel_launch(void* const* d_in, const int* in_sizes, int n_in,
                              void* d_out, int out_size) {
    const int*   tl   = (const int*)d_in[0];
    const float* dh   = (const float*)d_in[1];
    const float* enc  = (const float*)d_in[2];
    const float* emb  = (const float*)d_in[3];
    const float* W1   = (const float*)d_in[4];
    const float* b1   = (const float*)d_in[5];
    const float* W2   = (const float*)d_in[6];
    // d_in[7] = b2 (softmax-invariant, skipped)
    const float* Wih  = (const float*)d_in[8];
    const float* Whh  = (const float*)d_in[9];
    const float* bih  = (const float*)d_in[10];
    const float* bhh  = (const float*)d_in[11];
    const float* Wout = (const float*)d_in[12];
    const float* bout = (const float*)d_in[13];

    float* pred = (float*)d_out;                 // [128, 32000]
    float* hout = pred + (size_t)Bb * Vv;        // [128, 1024]

    __half *ench, *w1e, *dhh, *xh, *c1h;
    float *hbp, *part, *alpha, *gx, *gh;
    cudaGetSymbolAddress((void**)&ench,  g_ench);
    cudaGetSymbolAddress((void**)&w1e,   g_w1e);
    cudaGetSymbolAddress((void**)&dhh,   g_dhh);
    cudaGetSymbolAddress((void**)&xh,    g_xh);
    cudaGetSymbolAddress((void**)&c1h,   g_c1h);
    cudaGetSymbolAddress((void**)&hbp,   g_hb);
    cudaGetSymbolAddress((void**)&part,  g_part);
    cudaGetSymbolAddress((void**)&alpha, g_alpha);
    cudaGetSymbolAddress((void**)&gx,    g_gx);
    cudaGetSymbolAddress((void**)&gh,    g_gh);

    cudaFuncSetAttribute(k_merged1, cudaFuncAttributeMaxDynamicSharedMemorySize, DSMEM_BYTES);
    cudaFuncSetAttribute(k_merged2, cudaFuncAttributeMaxDynamicSharedMemorySize, DSMEM_BYTES);
    cudaFuncSetAttribute(gemm_hf<0>, cudaFuncAttributeMaxDynamicSharedMemorySize, DSMEM_BYTES);
    cudaFuncSetAttribute(gemm_hf<2>, cudaFuncAttributeMaxDynamicSharedMemorySize, DSMEM_BYTES);

    // 0) conversions: enc -> fp16, W1[:, :2048] -> fp16, dh -> fp16
    k_cvt4<<<32768, 256>>>((const float4*)enc, (uint2*)ench, (Ss * Bb * 2 * Hh) / 4);
    k_cvt_w1e<<<2048, 256>>>(W1, w1e);
    k_cvt4<<<128, 256>>>((const float4*)dh, (uint2*)dhh, (Bb * Hh) / 4);

    // 1) embeddings -> xh[:, :512], c1h[:, 3072:]
    k_embed<<<Bb, 512>>>(tl, emb, xh, c1h);

    // 2) hb = dh @ W1[:, 2048:3072]^T + b1   (M=128, N=1024, K=1024)
    gemm_hf<0><<<dim3(8, 1), 128, DSMEM_BYTES>>>(dhh, W1 + 2048, b1, hbp,
                                                 Bb, Hh, Hh, 3 * Hh, Hh,
                                                 nullptr, nullptr);

    // 3) merged: energy GEMM (1024 CTAs) + pred-embeds (250 CTAs, writes pred+bout)
    k_merged1<<<1274, 128, DSMEM_BYTES>>>(ench, w1e, hbp, W2, part,
                                          c1h, Wout, bout, pred);

    // 4) combine partials + softmax over s  -> alpha[s][b]
    k_softmax<<<Bb, Ss>>>(part, alpha);

    // 5) context a -> xh[:, 512:], c1h[:, 1024:3072]
    k_context<<<Bb, 512>>>(enc, alpha, xh, c1h);

    // 6) merged: gx (24) + gh (24) + pred-a (250, pred += acc)
    k_merged2<<<298, 128, DSMEM_BYTES>>>(xh, Wih, bih, gx,
                                         dhh, Whh, bhh, gh,
                                         c1h, Wout, pred);

    // 7) GRU elementwise -> h_new (output tail, fp32) and c1h[:, :1024]
    k_gru<<<Bb, Hh>>>(dh, gx, gh, hout, c1h);

    // 8) pred += h_new @ Wout[:, :1024]^T   (K=1024)
    gemm_hf<2><<<dim3(250, 1), 128, DSMEM_BYTES>>>(c1h, Wout, nullptr, pred,
                                                   Bb, Hh, 3584, 3584, Vv,
                                                   nullptr, nullptr);
}